// round 2
// baseline (speedup 1.0000x reference)
#include <cuda_runtime.h>
#include <cuda_bf16.h>
#include <float.h>

#define FULL 0xFFFFFFFFu

static constexpr int B = 4;
static constexpr int N = 8192;
static constexpr int M = 2048;
static constexpr int F = 256;
static constexpr int K = 16;
static constexpr int OUTC = 3 + F;      // 259
static constexpr int QPW = 4;           // queries per warp
static constexpr int KNN_BLOCKS = (B * M) / (16 * QPW);   // 128 (16 warps/block)
static constexpr int TR_TILES_PER_B = (F / 32) * (N / 128);  // 8*64 = 512
static constexpr int TR_BLOCKS = B * TR_TILES_PER_B;         // 2048

// Scratch (device globals — no allocation allowed)
__device__ float g_featT[(size_t)B * N * F];   // 32MB transposed features (B,N,F)
__device__ int   g_idx[(size_t)B * M * K];
__device__ float g_w[(size_t)B * M * K];

// ---------------------------------------------------------------------------
// Fused kernel: blocks [0, KNN_BLOCKS) do KNN (smem/issue-bound, DRAM idle),
// blocks [KNN_BLOCKS, KNN_BLOCKS+TR_BLOCKS) do the feature transpose
// (pure DRAM streaming) — they overlap inside one launch.
//
// KNN: warp handles QPW=4 queries. Ranking key s = |p|^2 - 2 q.p (|q|^2
// dropped: monotone per query, softmax shift-invariant). Points staged to
// shared as float4(x,y,z,|p|^2) in 2048-point chunks; each LDS.128 tile of
// 32 points is scored against all 4 queries. Warp-distributed sorted top-32
// list per query (lane i = i-th smallest; lanes 0..15 = exact top-16),
// guarded by a lazily refreshed 16th-smallest threshold.
// ---------------------------------------------------------------------------
__global__ __launch_bounds__(512, 2) void fused_knn_transpose(
    const float* __restrict__ pc,     // (B,3,N)
    const float* __restrict__ qc,     // (B,3,M)
    const float* __restrict__ temperature,
    const float* __restrict__ feat,   // (B,F,N)
    float* __restrict__ out)          // (B,259,M)
{
    __shared__ __align__(16) unsigned char smem_raw[32768];

    if (blockIdx.x < KNN_BLOCKS) {
        // ===================== KNN part =====================
        float4* s_pts = (float4*)smem_raw;    // 2048 * 16B = 32KB

        const int tid  = threadIdx.x;
        const int lane = tid & 31;
        const int wid  = tid >> 5;
        const int b    = blockIdx.x >> 5;                 // 32 blocks per batch
        const int q0   = ((blockIdx.x & 31) * 16 + wid) * QPW;

        const float* pcb = pc + (size_t)b * 3 * N;
        const float* qcb = qc + (size_t)b * 3 * M;

        float ax[QPW], ay[QPW], az[QPW], kd[QPW], thr[QPW];
        int   ki[QPW];
        #pragma unroll
        for (int q = 0; q < QPW; ++q) {
            ax[q] = -2.0f * qcb[q0 + q];
            ay[q] = -2.0f * qcb[M + q0 + q];
            az[q] = -2.0f * qcb[2 * M + q0 + q];
            kd[q] = FLT_MAX; ki[q] = 0; thr[q] = FLT_MAX;
        }

        for (int c = 0; c < 4; ++c) {
            __syncthreads();
            for (int i = tid; i < 2048; i += 512) {
                int n = c * 2048 + i;
                float x = pcb[n];
                float y = pcb[N + n];
                float z = pcb[2 * N + n];
                s_pts[i] = make_float4(x, y, z, fmaf(x, x, fmaf(y, y, z * z)));
            }
            __syncthreads();

            #pragma unroll 2
            for (int t = 0; t < 64; ++t) {
                float4 p = s_pts[t * 32 + lane];
                int nbase = c * 2048 + t * 32;
                #pragma unroll
                for (int q = 0; q < QPW; ++q) {
                    float s = fmaf(ax[q], p.x, p.w);
                    s = fmaf(ay[q], p.y, s);
                    s = fmaf(az[q], p.z, s);
                    unsigned mask = __ballot_sync(FULL, s < thr[q]);
                    if (mask) {
                        do {
                            int src = __ffs(mask) - 1;
                            mask &= mask - 1;
                            float cd = __shfl_sync(FULL, s, src);
                            int   cn = nbase + src;
                            int pos = __popc(__ballot_sync(FULL, kd[q] < cd));
                            float ud = __shfl_up_sync(FULL, kd[q], 1);
                            int   ui = __shfl_up_sync(FULL, ki[q], 1);
                            if (lane >= pos) {
                                kd[q] = (lane == pos) ? cd : ud;
                                ki[q] = (lane == pos) ? cn : ui;
                            }
                        } while (mask);
                        thr[q] = __shfl_sync(FULL, kd[q], 15);
                    }
                }
            }
        }

        // softmax over 16 smallest (shift-invariant in s) + projected points
        float tv = *temperature;
        float inv_sigma = 1.0f / fmaxf(tv * tv, 1e-4f);

        #pragma unroll
        for (int q = 0; q < QPW; ++q) {
            int m = q0 + q;
            float s0 = __shfl_sync(FULL, kd[q], 0);
            float ev = (lane < K) ? __expf((s0 - kd[q]) * inv_sigma) : 0.0f;
            float sum = ev;
            #pragma unroll
            for (int o = 16; o; o >>= 1) sum += __shfl_xor_sync(FULL, sum, o);
            float w = ev / sum;

            float px = pcb[ki[q]];
            float py = pcb[N + ki[q]];
            float pz = pcb[2 * N + ki[q]];
            float sx = w * px, sy = w * py, sz = w * pz;
            #pragma unroll
            for (int o = 16; o; o >>= 1) {
                sx += __shfl_xor_sync(FULL, sx, o);
                sy += __shfl_xor_sync(FULL, sy, o);
                sz += __shfl_xor_sync(FULL, sz, o);
            }
            if (lane == 0) {
                out[((size_t)b * OUTC + 0) * M + m] = sx;
                out[((size_t)b * OUTC + 1) * M + m] = sy;
                out[((size_t)b * OUTC + 2) * M + m] = sz;
            }
            if (lane < K) {
                size_t gq = (size_t)b * M + m;
                g_idx[gq * K + lane] = ki[q];
                g_w[gq * K + lane]   = w;
            }
        }
    } else {
        // ===================== transpose part =====================
        // (B,F,N) -> (B,N,F); tile = 32 f x 128 n per block
        float (*tile)[129] = (float (*)[129])smem_raw;   // 32*129*4 = 16512B

        int bid = blockIdx.x - KNN_BLOCKS;
        int b   = bid >> 9;                 // 512 tiles per batch
        int r   = bid & 511;
        int fb  = r >> 6;                   // 0..7  (f block of 32)
        int nb  = r & 63;                   // 0..63 (n block of 128)

        int tx = threadIdx.x & 127;         // n within tile
        int ty = threadIdx.x >> 7;          // 0..3
        const float* src = feat + ((size_t)b * F + fb * 32) * N + nb * 128;
        #pragma unroll
        for (int j = ty; j < 32; j += 4)
            tile[j][tx] = src[(size_t)j * N + tx];
        __syncthreads();

        int cx = threadIdx.x & 31;          // f within tile
        int cy = threadIdx.x >> 5;          // 0..15
        float* dst = g_featT + ((size_t)b * N + nb * 128) * F + fb * 32;
        #pragma unroll
        for (int j = cy; j < 128; j += 16)
            dst[(size_t)j * F + cx] = tile[cx][j];
    }
}

// ---------------------------------------------------------------------------
// Feature propagation. Block = 1024 threads = 32 queries.
// Warp per query: 16 neighbors x 2 LDG.128 per lane (contiguous 1KB vectors,
// resident in L2), stage to shared, write out coalesced in (259,M).
// ---------------------------------------------------------------------------
__global__ __launch_bounds__(1024) void feat_kernel(float* __restrict__ out)
{
    __shared__ float so[32][260];

    const int tid  = threadIdx.x;
    const int lane = tid & 31;
    const int wid  = tid >> 5;
    const int b    = blockIdx.x >> 6;           // 64 blocks per batch
    const int m0   = (blockIdx.x & 63) * 32;
    const int m    = m0 + wid;
    const size_t gq = (size_t)b * M + m;

    int   iv = 0;
    float wv = 0.0f;
    if (lane < K) {
        iv = g_idx[gq * K + lane];
        wv = g_w[gq * K + lane];
    }

    float4 accA = make_float4(0.f, 0.f, 0.f, 0.f);
    float4 accB = make_float4(0.f, 0.f, 0.f, 0.f);

    #pragma unroll
    for (int j = 0; j < K; ++j) {
        float wj = __shfl_sync(FULL, wv, j);
        int   ij = __shfl_sync(FULL, iv, j);
        const float4* base = (const float4*)(g_featT + ((size_t)b * N + ij) * F);
        float4 u = base[lane];
        float4 v = base[32 + lane];
        accA.x = fmaf(wj, u.x, accA.x);
        accA.y = fmaf(wj, u.y, accA.y);
        accA.z = fmaf(wj, u.z, accA.z);
        accA.w = fmaf(wj, u.w, accA.w);
        accB.x = fmaf(wj, v.x, accB.x);
        accB.y = fmaf(wj, v.y, accB.y);
        accB.z = fmaf(wj, v.z, accB.z);
        accB.w = fmaf(wj, v.w, accB.w);
    }

    *(float4*)&so[wid][4 * lane]       = accA;
    *(float4*)&so[wid][128 + 4 * lane] = accB;
    __syncthreads();

    #pragma unroll
    for (int r = 0; r < 8; ++r) {
        int f = wid * 8 + r;
        out[((size_t)b * OUTC + 3 + f) * M + m0 + lane] = so[lane][f];
    }
}

// ---------------------------------------------------------------------------
extern "C" void kernel_launch(void* const* d_in, const int* in_sizes, int n_in,
                              void* d_out, int out_size)
{
    const float* pc   = (const float*)d_in[0];  // point_cloud (B,3,N)
    const float* qc   = (const float*)d_in[1];  // query_cloud (B,3,M)
    const float* feat = (const float*)d_in[2];  // point_features (B,F,N)
    const float* temp = (const float*)d_in[3];  // temperature scalar
    float* out = (float*)d_out;

    fused_knn_transpose<<<KNN_BLOCKS + TR_BLOCKS, 512>>>(pc, qc, temp, feat, out);
    feat_kernel<<<(B * M) / 32, 1024>>>(out);
}

// round 3
// speedup vs baseline: 1.0731x; 1.0731x over previous
#include <cuda_runtime.h>
#include <cuda_bf16.h>
#include <float.h>

#define FULL 0xFFFFFFFFu

static constexpr int B = 4;
static constexpr int N = 8192;
static constexpr int M = 2048;
static constexpr int F = 256;
static constexpr int K = 16;
static constexpr int OUTC = 3 + F;      // 259
static constexpr int QPW = 4;           // queries per warp
static constexpr int KNN_WARPS_PER_BLK = 4;    // 128-thread blocks
static constexpr int KNN_Q_PER_BLK = KNN_WARPS_PER_BLK * QPW;          // 16
static constexpr int KNN_BLOCKS = (B * M) / KNN_Q_PER_BLK;             // 512
static constexpr int KNN_BLKS_PER_B = KNN_BLOCKS / B;                  // 128
static constexpr int TR_TILES_PER_B = (F / 32) * (N / 128);            // 512
static constexpr int TR_BLOCKS = B * TR_TILES_PER_B;                   // 2048

// Scratch (device globals — no allocation allowed)
__device__ float g_featT[(size_t)B * N * F];   // 32MB transposed features (B,N,F)
__device__ int   g_idx[(size_t)B * M * K];
__device__ float g_w[(size_t)B * M * K];

// ---------------------------------------------------------------------------
// Fused kernel, 128-thread blocks.
//   blocks [0, 512):      KNN, 4 warps x 4 queries each (smem/issue-bound)
//   blocks [512, 2560):   feature transpose (DRAM streaming) — co-resident
//                         with KNN blocks, fills idle issue slots + DRAM.
// KNN ranking key s = |p|^2 - 2 q.p (|q|^2 dropped: monotone per query,
// softmax shift-invariant). Points staged to shared as float4(x,y,z,|p|^2)
// in 2048-point chunks; each 32-point LDS.128 tile scored against 4 queries.
// Warp-distributed sorted top list (lane i = i-th smallest, lanes 0..15 =
// exact top-16), guarded by lazily refreshed 16th-smallest threshold.
// ---------------------------------------------------------------------------
__global__ __launch_bounds__(128) void fused_knn_transpose(
    const float* __restrict__ pc,     // (B,3,N)
    const float* __restrict__ qc,     // (B,3,M)
    const float* __restrict__ temperature,
    const float* __restrict__ feat,   // (B,F,N)
    float* __restrict__ out)          // (B,259,M)
{
    __shared__ __align__(16) unsigned char smem_raw[32768];

    if (blockIdx.x < KNN_BLOCKS) {
        // ===================== KNN =====================
        float4* s_pts = (float4*)smem_raw;    // 2048 * 16B = 32KB

        const int tid  = threadIdx.x;
        const int lane = tid & 31;
        const int wid  = tid >> 5;
        const int b    = blockIdx.x / KNN_BLKS_PER_B;
        const int q0   = ((blockIdx.x % KNN_BLKS_PER_B) * KNN_WARPS_PER_BLK + wid) * QPW;

        const float* pcb = pc + (size_t)b * 3 * N;
        const float* qcb = qc + (size_t)b * 3 * M;

        float ax[QPW], ay[QPW], az[QPW], kd[QPW], thr[QPW];
        int   ki[QPW];
        #pragma unroll
        for (int q = 0; q < QPW; ++q) {
            ax[q] = -2.0f * qcb[q0 + q];
            ay[q] = -2.0f * qcb[M + q0 + q];
            az[q] = -2.0f * qcb[2 * M + q0 + q];
            kd[q] = FLT_MAX; ki[q] = 0; thr[q] = FLT_MAX;
        }

        for (int c = 0; c < 4; ++c) {
            __syncthreads();
            #pragma unroll 4
            for (int i = tid; i < 2048; i += 128) {
                int n = c * 2048 + i;
                float x = pcb[n];
                float y = pcb[N + n];
                float z = pcb[2 * N + n];
                s_pts[i] = make_float4(x, y, z, fmaf(x, x, fmaf(y, y, z * z)));
            }
            __syncthreads();

            #pragma unroll 2
            for (int t = 0; t < 64; ++t) {
                float4 p = s_pts[t * 32 + lane];
                int nbase = c * 2048 + t * 32;
                #pragma unroll
                for (int q = 0; q < QPW; ++q) {
                    float s = fmaf(ax[q], p.x, p.w);
                    s = fmaf(ay[q], p.y, s);
                    s = fmaf(az[q], p.z, s);
                    unsigned mask = __ballot_sync(FULL, s < thr[q]);
                    if (mask) {
                        do {
                            int src = __ffs(mask) - 1;
                            mask &= mask - 1;
                            float cd = __shfl_sync(FULL, s, src);
                            int   cn = nbase + src;
                            int pos = __popc(__ballot_sync(FULL, kd[q] < cd));
                            float ud = __shfl_up_sync(FULL, kd[q], 1);
                            int   ui = __shfl_up_sync(FULL, ki[q], 1);
                            if (lane >= pos) {
                                kd[q] = (lane == pos) ? cd : ud;
                                ki[q] = (lane == pos) ? cn : ui;
                            }
                        } while (mask);
                        thr[q] = __shfl_sync(FULL, kd[q], 15);
                    }
                }
            }
        }

        // softmax over 16 smallest (shift-invariant in s) + projected points
        float tv = *temperature;
        float inv_sigma = 1.0f / fmaxf(tv * tv, 1e-4f);

        #pragma unroll
        for (int q = 0; q < QPW; ++q) {
            int m = q0 + q;
            float s0 = __shfl_sync(FULL, kd[q], 0);
            float ev = (lane < K) ? __expf((s0 - kd[q]) * inv_sigma) : 0.0f;
            float sum = ev;
            #pragma unroll
            for (int o = 16; o; o >>= 1) sum += __shfl_xor_sync(FULL, sum, o);
            float w = ev / sum;

            float px = pcb[ki[q]];
            float py = pcb[N + ki[q]];
            float pz = pcb[2 * N + ki[q]];
            float sx = w * px, sy = w * py, sz = w * pz;
            #pragma unroll
            for (int o = 16; o; o >>= 1) {
                sx += __shfl_xor_sync(FULL, sx, o);
                sy += __shfl_xor_sync(FULL, sy, o);
                sz += __shfl_xor_sync(FULL, sz, o);
            }
            if (lane == 0) {
                out[((size_t)b * OUTC + 0) * M + m] = sx;
                out[((size_t)b * OUTC + 1) * M + m] = sy;
                out[((size_t)b * OUTC + 2) * M + m] = sz;
            }
            if (lane < K) {
                size_t gq = (size_t)b * M + m;
                g_idx[gq * K + lane] = ki[q];
                g_w[gq * K + lane]   = w;
            }
        }
    } else {
        // ===================== transpose =====================
        // (B,F,N) -> (B,N,F); tile = 32 f x 128 n per block, 128 threads
        float (*tile)[129] = (float (*)[129])smem_raw;   // 32*129*4 = 16512B

        int bid = blockIdx.x - KNN_BLOCKS;
        int b   = bid >> 9;                 // 512 tiles per batch
        int r   = bid & 511;
        int fb  = r >> 6;                   // 0..7  (f block of 32)
        int nb  = r & 63;                   // 0..63 (n block of 128)

        int tx = threadIdx.x;               // n within tile (0..127)
        const float* src = feat + ((size_t)b * F + fb * 32) * N + nb * 128;
        #pragma unroll 8
        for (int j = 0; j < 32; ++j)
            tile[j][tx] = src[(size_t)j * N + tx];
        __syncthreads();

        int cx = threadIdx.x & 31;          // f within tile
        int cy = threadIdx.x >> 5;          // 0..3
        float* dst = g_featT + ((size_t)b * N + nb * 128) * F + fb * 32;
        #pragma unroll 8
        for (int j = cy; j < 128; j += 4)
            dst[(size_t)j * F + cx] = tile[cx][j];
    }
}

// ---------------------------------------------------------------------------
// Feature propagation. Block = 512 threads = 16 queries (512 blocks — avoids
// the 1.7-blocks/SM wave quantization seen at 1024 threads / 256 blocks).
// Warp per query: 16 neighbors x 2 LDG.128 per lane (contiguous 1KB vectors,
// L2-resident), stage to shared, write out coalesced in (259,M).
// ---------------------------------------------------------------------------
__global__ __launch_bounds__(512) void feat_kernel(float* __restrict__ out)
{
    __shared__ float so[16][260];

    const int tid  = threadIdx.x;
    const int lane = tid & 31;
    const int wid  = tid >> 5;
    const int b    = blockIdx.x >> 7;            // 128 blocks per batch
    const int m0   = (blockIdx.x & 127) * 16;
    const int m    = m0 + wid;
    const size_t gq = (size_t)b * M + m;

    int   iv = 0;
    float wv = 0.0f;
    if (lane < K) {
        iv = g_idx[gq * K + lane];
        wv = g_w[gq * K + lane];
    }

    float4 accA = make_float4(0.f, 0.f, 0.f, 0.f);
    float4 accB = make_float4(0.f, 0.f, 0.f, 0.f);

    #pragma unroll
    for (int j = 0; j < K; ++j) {
        float wj = __shfl_sync(FULL, wv, j);
        int   ij = __shfl_sync(FULL, iv, j);
        const float4* base = (const float4*)(g_featT + ((size_t)b * N + ij) * F);
        float4 u = base[lane];
        float4 v = base[32 + lane];
        accA.x = fmaf(wj, u.x, accA.x);
        accA.y = fmaf(wj, u.y, accA.y);
        accA.z = fmaf(wj, u.z, accA.z);
        accA.w = fmaf(wj, u.w, accA.w);
        accB.x = fmaf(wj, v.x, accB.x);
        accB.y = fmaf(wj, v.y, accB.y);
        accB.z = fmaf(wj, v.z, accB.z);
        accB.w = fmaf(wj, v.w, accB.w);
    }

    *(float4*)&so[wid][4 * lane]       = accA;
    *(float4*)&so[wid][128 + 4 * lane] = accB;
    __syncthreads();

    // warp wid covers f rows [wid*16, wid*16+16); lane -> (f pair, mLocal)
    #pragma unroll
    for (int r = 0; r < 8; ++r) {
        int f  = wid * 16 + r * 2 + (lane >> 4);
        int ml = lane & 15;
        out[((size_t)b * OUTC + 3 + f) * M + m0 + ml] = so[ml][f];
    }
}

// ---------------------------------------------------------------------------
extern "C" void kernel_launch(void* const* d_in, const int* in_sizes, int n_in,
                              void* d_out, int out_size)
{
    const float* pc   = (const float*)d_in[0];  // point_cloud (B,3,N)
    const float* qc   = (const float*)d_in[1];  // query_cloud (B,3,M)
    const float* feat = (const float*)d_in[2];  // point_features (B,F,N)
    const float* temp = (const float*)d_in[3];  // temperature scalar
    float* out = (float*)d_out;

    fused_knn_transpose<<<KNN_BLOCKS + TR_BLOCKS, 128>>>(pc, qc, temp, feat, out);
    feat_kernel<<<(B * M) / 16, 512>>>(out);
}

// round 9
// speedup vs baseline: 1.5719x; 1.4649x over previous
#include <cuda_runtime.h>
#include <cuda_bf16.h>
#include <float.h>

#define FULL 0xFFFFFFFFu

static constexpr int B = 4;
static constexpr int N = 8192;
static constexpr int M = 2048;
static constexpr int F = 256;
static constexpr int K = 16;
static constexpr int OUTC = 3 + F;  // 259

static constexpr int KNNB = (B * M) / 16;              // 512 knn blocks
static constexpr int TRB  = B * (F / 32) * (N / 128);  // 2048 transpose tiles

// Scratch (device globals — no allocation allowed)
__device__ float g_featT[(size_t)B * N * F];   // 32MB transposed features (B,N,F)
__device__ int   g_idx[(size_t)B * M * K];
__device__ float g_w[(size_t)B * M * K];

// ---------------------------------------------------------------------------
// Fused kernel, 512-thread blocks.
//   blocks [0, 512):     KNN — EXACT R1 semantics (warp per query, brute-force
//                        scan of all 8192 points in original order, key
//                        s = |p|^2 - 2 q.p via the same fmaf chain).
//   blocks [512, 2560):  feature transpose (B,F,N)->(B,N,F), one 32f x 128n
//                        tile per block (R2-proven geometry) — co-resident
//                        DRAM streaming overlapped with the smem-bound KNN.
// ---------------------------------------------------------------------------
__global__ __launch_bounds__(512) void fused_knn_transpose(
    const float* __restrict__ pc,     // (B,3,N)
    const float* __restrict__ qc,     // (B,3,M)
    const float* __restrict__ temperature,
    const float* __restrict__ feat,   // (B,F,N)
    float* __restrict__ out)          // (B,259,M)
{
    __shared__ __align__(16) unsigned char smem_raw[32768];

    if (blockIdx.x < KNNB) {
        // ===================== KNN (R1-exact) =====================
        float4* s_pts = (float4*)smem_raw;    // 2048 * 16B = 32KB

        const int tid  = threadIdx.x;
        const int lane = tid & 31;
        const int wid  = tid >> 5;
        const int b    = blockIdx.x >> 7;              // 128 blocks per batch
        const int m    = ((blockIdx.x & 127) << 4) + wid;

        const float* pcb = pc + (size_t)b * 3 * N;

        const float qx = qc[((size_t)b * 3 + 0) * M + m];
        const float qy = qc[((size_t)b * 3 + 1) * M + m];
        const float qz = qc[((size_t)b * 3 + 2) * M + m];
        const float ax = -2.0f * qx, ay = -2.0f * qy, az = -2.0f * qz;

        float kd = FLT_MAX;   // warp-sorted list: lane i = i-th smallest
        int   ki = 0;
        float thr = FLT_MAX;  // lazy copy of element 15 (16th smallest)

        for (int c = 0; c < 4; ++c) {
            __syncthreads();
            for (int i = tid; i < 2048; i += 512) {
                int n = c * 2048 + i;
                float x = pcb[n];
                float y = pcb[N + n];
                float z = pcb[2 * N + n];
                s_pts[i] = make_float4(x, y, z, fmaf(x, x, fmaf(y, y, z * z)));
            }
            __syncthreads();

            #pragma unroll 4
            for (int t = 0; t < 64; ++t) {
                float4 p = s_pts[t * 32 + lane];
                float s = fmaf(ax, p.x, p.w);
                s = fmaf(ay, p.y, s);
                s = fmaf(az, p.z, s);
                unsigned mask = __ballot_sync(FULL, s < thr);
                if (mask) {
                    int nbase = c * 2048 + t * 32;
                    do {
                        int src = __ffs(mask) - 1;
                        mask &= mask - 1;
                        float cd = __shfl_sync(FULL, s, src);
                        int   cn = nbase + src;
                        int pos = __popc(__ballot_sync(FULL, kd < cd));
                        float ud = __shfl_up_sync(FULL, kd, 1);
                        int   ui = __shfl_up_sync(FULL, ki, 1);
                        if (lane >= pos) {
                            kd = (lane == pos) ? cd : ud;
                            ki = (lane == pos) ? cn : ui;
                        }
                    } while (mask);
                    thr = __shfl_sync(FULL, kd, 15);
                }
            }
        }

        // softmax over the 16 smallest (shift-invariant in s)
        float tv = *temperature;
        float sigma = fmaxf(tv * tv, 1e-4f);
        float inv_sigma = 1.0f / sigma;
        float s0 = __shfl_sync(FULL, kd, 0);
        float ev = (lane < K) ? __expf((s0 - kd) * inv_sigma) : 0.0f;
        float sum = ev;
        #pragma unroll
        for (int o = 16; o; o >>= 1) sum += __shfl_xor_sync(FULL, sum, o);
        float w = ev / sum;

        // projected points: sum_k w_k * p_k (lanes >= 16 contribute w = 0)
        float px = pcb[ki];
        float py = pcb[N + ki];
        float pz = pcb[2 * N + ki];
        float sx = w * px, sy = w * py, sz = w * pz;
        #pragma unroll
        for (int o = 16; o; o >>= 1) {
            sx += __shfl_xor_sync(FULL, sx, o);
            sy += __shfl_xor_sync(FULL, sy, o);
            sz += __shfl_xor_sync(FULL, sz, o);
        }
        if (lane == 0) {
            out[((size_t)b * OUTC + 0) * M + m] = sx;
            out[((size_t)b * OUTC + 1) * M + m] = sy;
            out[((size_t)b * OUTC + 2) * M + m] = sz;
        }
        if (lane < K) {
            size_t gq = (size_t)b * M + m;
            g_idx[gq * K + lane] = ki;
            g_w[gq * K + lane]   = w;
        }
    } else {
        // ===================== transpose (R2-proven geometry) ==============
        // (B,F,N) -> (B,N,F); tile = 32 f x 128 n per block
        float (*tile)[129] = (float (*)[129])smem_raw;   // 32*129*4 = 16512B

        int t  = blockIdx.x - KNNB;         // 0..2047
        int b  = t >> 9;                    // 512 tiles per batch
        int r  = t & 511;
        int fb = r >> 6;                    // 0..7  (f block of 32)
        int nb = r & 63;                    // 0..63 (n block of 128)

        int tx = threadIdx.x & 127;         // n within tile
        int ty = threadIdx.x >> 7;          // 0..3
        const float* src = feat + ((size_t)b * F + fb * 32) * N + nb * 128;
        #pragma unroll
        for (int j = ty; j < 32; j += 4)
            tile[j][tx] = src[(size_t)j * N + tx];
        __syncthreads();

        int cx = threadIdx.x & 31;          // f within tile
        int cy = threadIdx.x >> 5;          // 0..15
        float* dst = g_featT + ((size_t)b * N + nb * 128) * F + fb * 32;
        #pragma unroll
        for (int j = cy; j < 128; j += 16)
            dst[(size_t)j * F + cx] = tile[cx][j];
    }
}

// ---------------------------------------------------------------------------
// Feature propagation (R3-proven). Block = 512 threads = 16 queries.
// Warp per query: 16 neighbors x 2 LDG.128 per lane (contiguous 1KB vectors,
// L2-resident), stage to shared, write out coalesced in (259,M).
// ---------------------------------------------------------------------------
__global__ __launch_bounds__(512) void feat_kernel(float* __restrict__ out)
{
    __shared__ float so[16][260];

    const int tid  = threadIdx.x;
    const int lane = tid & 31;
    const int wid  = tid >> 5;
    const int b    = blockIdx.x >> 7;            // 128 blocks per batch
    const int m0   = (blockIdx.x & 127) * 16;
    const int m    = m0 + wid;
    const size_t gq = (size_t)b * M + m;

    int   iv = 0;
    float wv = 0.0f;
    if (lane < K) {
        iv = g_idx[gq * K + lane];
        wv = g_w[gq * K + lane];
    }

    float4 accA = make_float4(0.f, 0.f, 0.f, 0.f);
    float4 accB = make_float4(0.f, 0.f, 0.f, 0.f);

    #pragma unroll
    for (int j = 0; j < K; ++j) {
        float wj = __shfl_sync(FULL, wv, j);
        int   ij = __shfl_sync(FULL, iv, j);
        const float4* base = (const float4*)(g_featT + ((size_t)b * N + ij) * F);
        float4 u = base[lane];
        float4 v = base[32 + lane];
        accA.x = fmaf(wj, u.x, accA.x);
        accA.y = fmaf(wj, u.y, accA.y);
        accA.z = fmaf(wj, u.z, accA.z);
        accA.w = fmaf(wj, u.w, accA.w);
        accB.x = fmaf(wj, v.x, accB.x);
        accB.y = fmaf(wj, v.y, accB.y);
        accB.z = fmaf(wj, v.z, accB.z);
        accB.w = fmaf(wj, v.w, accB.w);
    }

    *(float4*)&so[wid][4 * lane]       = accA;
    *(float4*)&so[wid][128 + 4 * lane] = accB;
    __syncthreads();

    // warp wid covers f rows [wid*16, wid*16+16); lane -> (f pair, mLocal)
    #pragma unroll
    for (int r = 0; r < 8; ++r) {
        int f  = wid * 16 + r * 2 + (lane >> 4);
        int ml = lane & 15;
        out[((size_t)b * OUTC + 3 + f) * M + m0 + ml] = so[ml][f];
    }
}

// ---------------------------------------------------------------------------
extern "C" void kernel_launch(void* const* d_in, const int* in_sizes, int n_in,
                              void* d_out, int out_size)
{
    const float* pc   = (const float*)d_in[0];  // point_cloud (B,3,N)
    const float* qc   = (const float*)d_in[1];  // query_cloud (B,3,M)
    const float* feat = (const float*)d_in[2];  // point_features (B,F,N)
    const float* temp = (const float*)d_in[3];  // temperature scalar
    float* out = (float*)d_out;

    fused_knn_transpose<<<KNNB + TRB, 512>>>(pc, qc, temp, feat, out);
    feat_kernel<<<(B * M) / 16, 512>>>(out);
}